// round 7
// baseline (speedup 1.0000x reference)
#include <cuda_runtime.h>
#include <math.h>
#include <stdint.h>

#define EMBED   1024
#define NHEADS  16
#define HDIM    64
#define BATCH   2
#define QLEN    2048
#define CLEN    2048
#define MROWS   (BATCH * QLEN)   // 4096
#define KP      (EMBED / 2)      // 512 u32 pairs per row

__device__ uint32_t g_Xqh[MROWS * KP];
__device__ uint32_t g_Xch[MROWS * KP];
__device__ uint32_t g_Wh[4][KP * EMBED];
__device__ uint32_t g_Qh[MROWS * KP];
__device__ uint32_t g_Kh[MROWS * KP];
__device__ float    g_Vf[MROWS * EMBED];
__device__ uint32_t g_Ah[MROWS * KP];

__device__ __forceinline__ uint32_t f2h2(float lo, float hi) {
    uint32_t r;
    asm("cvt.rn.f16x2.f32 %0, %1, %2;" : "=r"(r) : "f"(hi), "f"(lo));
    return r;
}

#define MMA_F16(d, a, b)                                                   \
    asm volatile(                                                          \
        "mma.sync.aligned.m16n8k16.row.col.f32.f16.f16.f32 "               \
        "{%0,%1,%2,%3}, {%4,%5,%6,%7}, {%8,%9}, {%0,%1,%2,%3};"            \
        : "+f"(d[0]), "+f"(d[1]), "+f"(d[2]), "+f"(d[3])                   \
        : "r"(a[0]), "r"(a[1]), "r"(a[2]), "r"(a[3]), "r"(b[0]), "r"(b[1]))

// ---------------------------------------------------------------------------
// Prepass: pack fp32 -> fp16 pairs.
// ---------------------------------------------------------------------------
__global__ void __launch_bounds__(256) prepack_kernel(
    const float* __restrict__ q, const float* __restrict__ ctx,
    const float* __restrict__ Wq, const float* __restrict__ Wk,
    const float* __restrict__ Wv, const float* __restrict__ Wo)
{
    const int z = blockIdx.z;
    const int stride = gridDim.x * blockDim.x;
    int i0 = blockIdx.x * blockDim.x + threadIdx.x;

    if (z < 2) {
        const float* src = (z == 0) ? q : ctx;
        uint2* dst = (uint2*)((z == 0) ? g_Xqh : g_Xch);
        const int count = MROWS * KP / 2;
        for (int i = i0; i < count; i += stride) {
            float4 v = ((const float4*)src)[i];
            dst[i] = make_uint2(f2h2(v.x, v.y), f2h2(v.z, v.w));
        }
    } else {
        const float* W = (z == 2) ? Wq : (z == 3) ? Wk : (z == 4) ? Wv : Wo;
        uint4* dst = (uint4*)g_Wh[z - 2];
        const int count = KP * EMBED / 4;
        for (int i = i0; i < count; i += stride) {
            int kp = i >> 8;
            int n4 = (i & 255) * 4;
            float4 a = *(const float4*)&W[(size_t)(2 * kp) * EMBED + n4];
            float4 b = *(const float4*)&W[(size_t)(2 * kp + 1) * EMBED + n4];
            dst[i] = make_uint4(f2h2(a.x, b.x), f2h2(a.y, b.y),
                                f2h2(a.z, b.z), f2h2(a.w, b.w));
        }
    }
}

// ---------------------------------------------------------------------------
// fp16 GEMM + bias: CTA 256x128, BK=16, double-buffered, 256 threads (8 warps),
// warp tile 64x64 (mt=4, nt=8).
// ---------------------------------------------------------------------------
#define PAH 12
#define PBH 136

__device__ __forceinline__ void gemm_h_body(
    const uint32_t* __restrict__ A, const uint32_t* __restrict__ W,
    const float* __restrict__ bias, void* __restrict__ Cout,
    int outHalf, float oscale, int bx, int by)
{
    __shared__ uint32_t As[2][256 * PAH];
    __shared__ uint32_t Bs[2][8 * PBH];

    const int tid  = threadIdx.x;
    const int lane = tid & 31;
    const int warp = tid >> 5;
    const int g    = lane >> 2;
    const int tg   = lane & 3;
    const int wr   = (warp >> 1) * 64;   // 0,64,128,192
    const int wc   = (warp & 1) * 64;
    const int rowBase = by * 256;
    const int colBase = bx * 128;

    const int am  = tid >> 1;          // A rows am, am+128
    const int akp = (tid & 1) * 4;
    const int bkp = tid >> 5;          // 0..7
    const int bn  = (tid & 31) * 4;

    const uint32_t* Aptr = A + (size_t)(rowBase + am) * KP + akp;
    const uint32_t* Wptr = W + (size_t)bkp * EMBED + colBase + bn;

    float acc[4][8][4];
    #pragma unroll
    for (int mt = 0; mt < 4; mt++)
        #pragma unroll
        for (int nt = 0; nt < 8; nt++)
            #pragma unroll
            for (int e = 0; e < 4; e++) acc[mt][nt][e] = 0.f;

    uint4 ra0, ra1, rb;
    auto ldg = [&](int kt) {
        ra0 = *(const uint4*)(Aptr + kt * 8);
        ra1 = *(const uint4*)(Aptr + (size_t)128 * KP + kt * 8);
        rb  = *(const uint4*)(Wptr + (size_t)(kt * 8) * EMBED);
    };
    auto sts = [&](int buf) {
        *(uint4*)&As[buf][am * PAH + akp]         = ra0;
        *(uint4*)&As[buf][(am + 128) * PAH + akp] = ra1;
        *(uint4*)&Bs[buf][bkp * PBH + bn]         = rb;
    };

    ldg(0);
    sts(0);
    __syncthreads();

    int buf = 0;
    for (int kt = 0; kt < 64; kt++) {
        if (kt + 1 < 64) ldg(kt + 1);

        uint32_t a[4][4];
        #pragma unroll
        for (int mt = 0; mt < 4; mt++) {
            int m = wr + mt * 16 + g;
            a[mt][0] = As[buf][m * PAH + tg];
            a[mt][1] = As[buf][(m + 8) * PAH + tg];
            a[mt][2] = As[buf][m * PAH + tg + 4];
            a[mt][3] = As[buf][(m + 8) * PAH + tg + 4];
        }
        #pragma unroll
        for (int nt = 0; nt < 8; nt++) {
            uint32_t b[2];
            int n = wc + nt * 8 + g;
            b[0] = Bs[buf][tg * PBH + n];
            b[1] = Bs[buf][(tg + 4) * PBH + n];
            #pragma unroll
            for (int mt = 0; mt < 4; mt++)
                MMA_F16(acc[mt][nt], a[mt], b);
        }
        if (kt + 1 < 64) sts(buf ^ 1);
        __syncthreads();
        buf ^= 1;
    }

    if (outHalf) {
        uint32_t* C = (uint32_t*)Cout;
        #pragma unroll
        for (int mt = 0; mt < 4; mt++) {
            #pragma unroll
            for (int nt = 0; nt < 8; nt++) {
                int row  = rowBase + wr + mt * 16 + g;
                int col  = colBase + wc + nt * 8 + 2 * tg;
                int colp = col >> 1;
                float2 bv = *(const float2*)&bias[col];
                C[(size_t)row * KP + colp] =
                    f2h2((acc[mt][nt][0] + bv.x) * oscale,
                         (acc[mt][nt][1] + bv.y) * oscale);
                C[(size_t)(row + 8) * KP + colp] =
                    f2h2((acc[mt][nt][2] + bv.x) * oscale,
                         (acc[mt][nt][3] + bv.y) * oscale);
            }
        }
    } else {
        float* C = (float*)Cout;
        #pragma unroll
        for (int mt = 0; mt < 4; mt++) {
            #pragma unroll
            for (int nt = 0; nt < 8; nt++) {
                int row = rowBase + wr + mt * 16 + g;
                int col = colBase + wc + nt * 8 + 2 * tg;
                float2 bv = *(const float2*)&bias[col];
                float2 r0 = make_float2(acc[mt][nt][0] + bv.x, acc[mt][nt][1] + bv.y);
                float2 r1 = make_float2(acc[mt][nt][2] + bv.x, acc[mt][nt][3] + bv.y);
                *(float2*)&C[(size_t)row * EMBED + col]       = r0;
                *(float2*)&C[(size_t)(row + 8) * EMBED + col] = r1;
            }
        }
    }
}

__global__ void __launch_bounds__(256) gemm_qkv_kernel(
    const float* __restrict__ bq, const float* __restrict__ bk,
    const float* __restrict__ bv)
{
    const int z = blockIdx.z;
    if (z == 0)      gemm_h_body(g_Xqh, g_Wh[0], bq, g_Qh, 1, 0.125f, blockIdx.x, blockIdx.y);
    else if (z == 1) gemm_h_body(g_Xch, g_Wh[1], bk, g_Kh, 1, 1.0f,   blockIdx.x, blockIdx.y);
    else             gemm_h_body(g_Xch, g_Wh[2], bv, g_Vf, 0, 1.0f,   blockIdx.x, blockIdx.y);
}

__global__ void __launch_bounds__(256) gemm_o_kernel(
    const float* __restrict__ bo, float* __restrict__ out)
{
    gemm_h_body(g_Ah, g_Wh[3], bo, out, 0, 1.0f, blockIdx.x, blockIdx.y);
}

// ---------------------------------------------------------------------------
// Flash attention fp16, P kept in registers (C-layout == A-layout trick).
// q-tile 128, 4 warps x 32 rows; kv tiles of 64; K/V double-buffered.
// ---------------------------------------------------------------------------
#define PKH 36
#define PVH 72
#define PPH 36
#define FSM_TOTAL ((2 * 64 * PKH + 2 * 32 * PVH + 128 * PPH) * 4)

__global__ void __launch_bounds__(128) flash_h_kernel()
{
    extern __shared__ uint32_t sm[];
    uint32_t* Ks = sm;                                  // 2 x [64][PKH]
    uint32_t* Vs = sm + 2 * 64 * PKH;                   // 2 x [32][PVH]
    uint32_t* Qstage = sm + 2 * 64 * PKH + 2 * 32 * PVH; // [128][PPH]

    const int b  = blockIdx.z;
    const int h  = blockIdx.y;
    const int q0 = blockIdx.x * 128;
    const int tid  = threadIdx.x;
    const int lane = tid & 31;
    const int warp = tid >> 5;
    const int g    = lane >> 2;
    const int tg   = lane & 3;
    const int mrow = warp * 32;

    const uint32_t* Qb = g_Qh + (size_t)b * QLEN * KP + h * 32;
    const uint32_t* Kb = g_Kh + (size_t)b * CLEN * KP + h * 32;
    const float*    Vb = g_Vf + (size_t)b * CLEN * EMBED + h * HDIM;

    const int kvr = tid >> 3;
    const int dq  = (tid & 7) * 4;
    uint4 kpf[4];
    auto ldgK = [&](int kt) {
        #pragma unroll
        for (int i = 0; i < 4; i++)
            kpf[i] = *(const uint4*)&Kb[(size_t)(kt * 64 + kvr + 16 * i) * KP + dq];
    };
    auto stsK = [&](uint32_t* dst) {
        #pragma unroll
        for (int i = 0; i < 4; i++)
            *(uint4*)&dst[(kvr + 16 * i) * PKH + dq] = kpf[i];
    };

    const int va_ = tid >> 4;
    const int dcol = (tid & 15) * 4;
    float4 vpa[4], vpb[4];
    auto ldgV = [&](int kt) {
        #pragma unroll
        for (int i = 0; i < 4; i++) {
            int kv2 = kt * 64 + 2 * (va_ + 8 * i);
            vpa[i] = *(const float4*)&Vb[(size_t)kv2 * EMBED + dcol];
            vpb[i] = *(const float4*)&Vb[(size_t)(kv2 + 1) * EMBED + dcol];
        }
    };
    auto stsV = [&](uint32_t* dst) {
        #pragma unroll
        for (int i = 0; i < 4; i++) {
            uint4 u = make_uint4(f2h2(vpa[i].x, vpb[i].x), f2h2(vpa[i].y, vpb[i].y),
                                 f2h2(vpa[i].z, vpb[i].z), f2h2(vpa[i].w, vpb[i].w));
            *(uint4*)&dst[(va_ + 8 * i) * PVH + dcol] = u;
        }
    };

    // Stage Q tile: 128 rows x 32 dp
    #pragma unroll
    for (int i = 0; i < 8; i++) {
        int idx = tid + i * 128;
        int r = idx >> 3;
        int q4 = (idx & 7) * 4;
        uint4 v = *(const uint4*)&Qb[(size_t)(q0 + r) * KP + q4];
        *(uint4*)&Qstage[r * PPH + q4] = v;
    }
    ldgK(0);
    __syncthreads();

    uint32_t qf[2][4][4];
    #pragma unroll
    for (int mt = 0; mt < 2; mt++) {
        int m = mrow + mt * 16 + g;
        #pragma unroll
        for (int s = 0; s < 4; s++) {
            qf[mt][s][0] = Qstage[m * PPH + 8 * s + tg];
            qf[mt][s][1] = Qstage[(m + 8) * PPH + 8 * s + tg];
            qf[mt][s][2] = Qstage[m * PPH + 8 * s + tg + 4];
            qf[mt][s][3] = Qstage[(m + 8) * PPH + 8 * s + tg + 4];
        }
    }
    stsK(Ks);
    ldgV(0);
    stsV(Vs);
    __syncthreads();

    float m_[4], l_[4];
    #pragma unroll
    for (int i = 0; i < 4; i++) { m_[i] = -INFINITY; l_[i] = 0.f; }
    float o[2][8][4];
    #pragma unroll
    for (int mt = 0; mt < 2; mt++)
        #pragma unroll
        for (int nt = 0; nt < 8; nt++)
            #pragma unroll
            for (int e = 0; e < 4; e++) o[mt][nt][e] = 0.f;

    const int NT = CLEN / 64;
    for (int kt = 0; kt < NT; kt++) {
        const int buf = kt & 1;
        uint32_t* Kcur = Ks + buf * 64 * PKH;
        uint32_t* Vcur = Vs + buf * 32 * PVH;
        uint32_t* Knxt = Ks + (buf ^ 1) * 64 * PKH;
        uint32_t* Vnxt = Vs + (buf ^ 1) * 32 * PVH;

        if (kt + 1 < NT) ldgK(kt + 1);

        // ---- S = Q K^T ----
        float sacc[2][8][4];
        #pragma unroll
        for (int mt = 0; mt < 2; mt++)
            #pragma unroll
            for (int nt = 0; nt < 8; nt++)
                #pragma unroll
                for (int e = 0; e < 4; e++) sacc[mt][nt][e] = 0.f;

        #pragma unroll
        for (int s = 0; s < 4; s++) {
            #pragma unroll
            for (int nt = 0; nt < 8; nt++) {
                uint32_t bf[2];
                bf[0] = Kcur[(nt * 8 + g) * PKH + 8 * s + tg];
                bf[1] = Kcur[(nt * 8 + g) * PKH + 8 * s + tg + 4];
                MMA_F16(sacc[0][nt], qf[0][s], bf);
                MMA_F16(sacc[1][nt], qf[1][s], bf);
            }
        }

        if (kt + 1 < NT) {
            stsK(Knxt);
            ldgV(kt + 1);
        }

        // ---- online softmax; p values overwrite sacc (stay in regs) ----
        #pragma unroll
        for (int mt = 0; mt < 2; mt++) {
            float mx0 = -INFINITY, mx1 = -INFINITY;
            #pragma unroll
            for (int nt = 0; nt < 8; nt++) {
                mx0 = fmaxf(mx0, fmaxf(sacc[mt][nt][0], sacc[mt][nt][1]));
                mx1 = fmaxf(mx1, fmaxf(sacc[mt][nt][2], sacc[mt][nt][3]));
            }
            #pragma unroll
            for (int off = 1; off < 4; off <<= 1) {
                mx0 = fmaxf(mx0, __shfl_xor_sync(0xffffffffu, mx0, off));
                mx1 = fmaxf(mx1, __shfl_xor_sync(0xffffffffu, mx1, off));
            }
            float mn0 = fmaxf(m_[2 * mt],     mx0);
            float mn1 = fmaxf(m_[2 * mt + 1], mx1);
            float c0 = __expf(m_[2 * mt]     - mn0);
            float c1 = __expf(m_[2 * mt + 1] - mn1);

            float rs0 = 0.f, rs1 = 0.f;
            #pragma unroll
            for (int nt = 0; nt < 8; nt++) {
                sacc[mt][nt][0] = __expf(sacc[mt][nt][0] - mn0);
                sacc[mt][nt][1] = __expf(sacc[mt][nt][1] - mn0);
                sacc[mt][nt][2] = __expf(sacc[mt][nt][2] - mn1);
                sacc[mt][nt][3] = __expf(sacc[mt][nt][3] - mn1);
                rs0 += sacc[mt][nt][0] + sacc[mt][nt][1];
                rs1 += sacc[mt][nt][2] + sacc[mt][nt][3];
            }
            #pragma unroll
            for (int off = 1; off < 4; off <<= 1) {
                rs0 += __shfl_xor_sync(0xffffffffu, rs0, off);
                rs1 += __shfl_xor_sync(0xffffffffu, rs1, off);
            }
            l_[2 * mt]     = l_[2 * mt]     * c0 + rs0;
            l_[2 * mt + 1] = l_[2 * mt + 1] * c1 + rs1;
            m_[2 * mt]     = mn0;
            m_[2 * mt + 1] = mn1;
            #pragma unroll
            for (int nt = 0; nt < 8; nt++) {
                o[mt][nt][0] *= c0; o[mt][nt][1] *= c0;
                o[mt][nt][2] *= c1; o[mt][nt][3] *= c1;
            }
        }

        // ---- O += P V : P fragments packed directly from sacc regs ----
        #pragma unroll
        for (int s = 0; s < 4; s++) {
            uint32_t af[2][4];
            #pragma unroll
            for (int mt = 0; mt < 2; mt++) {
                af[mt][0] = f2h2(sacc[mt][2 * s][0],     sacc[mt][2 * s][1]);
                af[mt][1] = f2h2(sacc[mt][2 * s][2],     sacc[mt][2 * s][3]);
                af[mt][2] = f2h2(sacc[mt][2 * s + 1][0], sacc[mt][2 * s + 1][1]);
                af[mt][3] = f2h2(sacc[mt][2 * s + 1][2], sacc[mt][2 * s + 1][3]);
            }
            #pragma unroll
            for (int nt = 0; nt < 8; nt++) {
                uint32_t bf[2];
                bf[0] = Vcur[(8 * s + tg) * PVH + nt * 8 + g];
                bf[1] = Vcur[(8 * s + tg + 4) * PVH + nt * 8 + g];
                MMA_F16(o[0][nt], af[0], bf);
                MMA_F16(o[1][nt], af[1], bf);
            }
        }

        if (kt + 1 < NT) stsV(Vnxt);
        __syncthreads();
    }

    // normalize + write fp16 pairs to g_Ah
    uint32_t* Ab = g_Ah + (size_t)b * QLEN * KP + h * 32;
    #pragma unroll
    for (int mt = 0; mt < 2; mt++) {
        float i0 = 1.f / l_[2 * mt];
        float i1 = 1.f / l_[2 * mt + 1];
        int r0 = q0 + mrow + mt * 16 + g;
        #pragma unroll
        for (int nt = 0; nt < 8; nt++) {
            int colp = nt * 4 + tg;
            Ab[(size_t)r0 * KP + colp]       = f2h2(o[mt][nt][0] * i0, o[mt][nt][1] * i0);
            Ab[(size_t)(r0 + 8) * KP + colp] = f2h2(o[mt][nt][2] * i1, o[mt][nt][3] * i1);
        }
    }
}

// ---------------------------------------------------------------------------
extern "C" void kernel_launch(void* const* d_in, const int* in_sizes, int n_in,
                              void* d_out, int out_size)
{
    const float* query   = (const float*)d_in[0];
    const float* context = (const float*)d_in[1];
    const float* bq = (const float*)d_in[3];
    const float* bk = (const float*)d_in[5];
    const float* bv = (const float*)d_in[7];
    const float* bo = (const float*)d_in[9];
    const float* Wq = (const float*)d_in[2];
    const float* Wk = (const float*)d_in[4];
    const float* Wv = (const float*)d_in[6];
    const float* Wo = (const float*)d_in[8];
    float* out = (float*)d_out;

    prepack_kernel<<<dim3(256, 1, 6), 256>>>(query, context, Wq, Wk, Wv, Wo);

    dim3 gQKV(EMBED / 128, MROWS / 256, 3);   // (8, 16, 3)
    gemm_qkv_kernel<<<gQKV, 256>>>(bq, bk, bv);

    cudaFuncSetAttribute(flash_h_kernel,
                         cudaFuncAttributeMaxDynamicSharedMemorySize, FSM_TOTAL);
    flash_h_kernel<<<dim3(QLEN / 128, NHEADS, BATCH), 128, FSM_TOTAL>>>();

    dim3 gGemm(EMBED / 128, MROWS / 256);     // (8, 16)
    gemm_o_kernel<<<gGemm, 256>>>(bo, out);
}

// round 8
// speedup vs baseline: 1.1438x; 1.1438x over previous
#include <cuda_runtime.h>
#include <math.h>
#include <stdint.h>

#define EMBED   1024
#define NHEADS  16
#define HDIM    64
#define BATCH   2
#define QLEN    2048
#define CLEN    2048
#define MROWS   (BATCH * QLEN)   // 4096
#define KP      (EMBED / 2)      // 512 u32 pairs per row

__device__ uint32_t g_Xqh[MROWS * KP];
__device__ uint32_t g_Xch[MROWS * KP];
__device__ uint32_t g_Wh[4][KP * EMBED];
__device__ uint32_t g_Qh[MROWS * KP];
__device__ uint32_t g_Kh[MROWS * KP];
__device__ float    g_Vf[MROWS * EMBED];
__device__ uint32_t g_Ah[MROWS * KP];

__device__ __forceinline__ uint32_t f2h2(float lo, float hi) {
    uint32_t r;
    asm("cvt.rn.f16x2.f32 %0, %1, %2;" : "=r"(r) : "f"(hi), "f"(lo));
    return r;
}

#define MMA_F16(d, a, b)                                                   \
    asm volatile(                                                          \
        "mma.sync.aligned.m16n8k16.row.col.f32.f16.f16.f32 "               \
        "{%0,%1,%2,%3}, {%4,%5,%6,%7}, {%8,%9}, {%0,%1,%2,%3};"            \
        : "+f"(d[0]), "+f"(d[1]), "+f"(d[2]), "+f"(d[3])                   \
        : "r"(a[0]), "r"(a[1]), "r"(a[2]), "r"(a[3]), "r"(b[0]), "r"(b[1]))

// ---------------------------------------------------------------------------
// Prepass: pack fp32 -> fp16 pairs.
// ---------------------------------------------------------------------------
__global__ void __launch_bounds__(256) prepack_kernel(
    const float* __restrict__ q, const float* __restrict__ ctx,
    const float* __restrict__ Wq, const float* __restrict__ Wk,
    const float* __restrict__ Wv, const float* __restrict__ Wo)
{
    const int z = blockIdx.z;
    const int stride = gridDim.x * blockDim.x;
    int i0 = blockIdx.x * blockDim.x + threadIdx.x;

    if (z < 2) {
        const float* src = (z == 0) ? q : ctx;
        uint2* dst = (uint2*)((z == 0) ? g_Xqh : g_Xch);
        const int count = MROWS * KP / 2;
        for (int i = i0; i < count; i += stride) {
            float4 v = ((const float4*)src)[i];
            dst[i] = make_uint2(f2h2(v.x, v.y), f2h2(v.z, v.w));
        }
    } else {
        const float* W = (z == 2) ? Wq : (z == 3) ? Wk : (z == 4) ? Wv : Wo;
        uint4* dst = (uint4*)g_Wh[z - 2];
        const int count = KP * EMBED / 4;
        for (int i = i0; i < count; i += stride) {
            int kp = i >> 8;
            int n4 = (i & 255) * 4;
            float4 a = *(const float4*)&W[(size_t)(2 * kp) * EMBED + n4];
            float4 b = *(const float4*)&W[(size_t)(2 * kp + 1) * EMBED + n4];
            dst[i] = make_uint4(f2h2(a.x, b.x), f2h2(a.y, b.y),
                                f2h2(a.z, b.z), f2h2(a.w, b.w));
        }
    }
}

// ---------------------------------------------------------------------------
// fp16 GEMM + bias: CTA 128x128, BK=16, double-buffered, 128 threads
// (4 warps, 2x2 grid), warp tile 64x64 (mt=4, nt=8) — minimal fragment traffic.
// ---------------------------------------------------------------------------
#define PAH 12
#define PBH 136

__device__ __forceinline__ void gemm_h_body(
    const uint32_t* __restrict__ A, const uint32_t* __restrict__ W,
    const float* __restrict__ bias, void* __restrict__ Cout,
    int outHalf, float oscale, int bx, int by)
{
    __shared__ uint32_t As[2][128 * PAH];
    __shared__ uint32_t Bs[2][8 * PBH];

    const int tid  = threadIdx.x;
    const int lane = tid & 31;
    const int warp = tid >> 5;           // 0..3
    const int g    = lane >> 2;
    const int tg   = lane & 3;
    const int wr   = (warp >> 1) * 64;   // 0,64
    const int wc   = (warp & 1) * 64;    // 0,64
    const int rowBase = by * 128;
    const int colBase = bx * 128;

    const int am  = tid >> 1;            // A rows am, am+64
    const int akp = (tid & 1) * 4;
    const int bkp = tid >> 5;            // B kp rows bkp, bkp+4
    const int bn  = (tid & 31) * 4;

    const uint32_t* Aptr = A + (size_t)(rowBase + am) * KP + akp;
    const uint32_t* Wptr = W + (size_t)bkp * EMBED + colBase + bn;

    float acc[4][8][4];
    #pragma unroll
    for (int mt = 0; mt < 4; mt++)
        #pragma unroll
        for (int nt = 0; nt < 8; nt++)
            #pragma unroll
            for (int e = 0; e < 4; e++) acc[mt][nt][e] = 0.f;

    uint4 ra0, ra1, rb0, rb1;
    auto ldg = [&](int kt) {
        ra0 = *(const uint4*)(Aptr + kt * 8);
        ra1 = *(const uint4*)(Aptr + (size_t)64 * KP + kt * 8);
        rb0 = *(const uint4*)(Wptr + (size_t)(kt * 8) * EMBED);
        rb1 = *(const uint4*)(Wptr + (size_t)(kt * 8 + 4) * EMBED);
    };
    auto sts = [&](int buf) {
        *(uint4*)&As[buf][am * PAH + akp]        = ra0;
        *(uint4*)&As[buf][(am + 64) * PAH + akp] = ra1;
        *(uint4*)&Bs[buf][bkp * PBH + bn]        = rb0;
        *(uint4*)&Bs[buf][(bkp + 4) * PBH + bn]  = rb1;
    };

    ldg(0);
    sts(0);
    __syncthreads();

    int buf = 0;
    for (int kt = 0; kt < 64; kt++) {
        if (kt + 1 < 64) ldg(kt + 1);

        uint32_t a[4][4];
        #pragma unroll
        for (int mt = 0; mt < 4; mt++) {
            int m = wr + mt * 16 + g;
            a[mt][0] = As[buf][m * PAH + tg];
            a[mt][1] = As[buf][(m + 8) * PAH + tg];
            a[mt][2] = As[buf][m * PAH + tg + 4];
            a[mt][3] = As[buf][(m + 8) * PAH + tg + 4];
        }
        #pragma unroll
        for (int nt = 0; nt < 8; nt++) {
            uint32_t b[2];
            int n = wc + nt * 8 + g;
            b[0] = Bs[buf][tg * PBH + n];
            b[1] = Bs[buf][(tg + 4) * PBH + n];
            #pragma unroll
            for (int mt = 0; mt < 4; mt++)
                MMA_F16(acc[mt][nt], a[mt], b);
        }
        if (kt + 1 < 64) sts(buf ^ 1);
        __syncthreads();
        buf ^= 1;
    }

    if (outHalf) {
        uint32_t* C = (uint32_t*)Cout;
        #pragma unroll
        for (int mt = 0; mt < 4; mt++) {
            #pragma unroll
            for (int nt = 0; nt < 8; nt++) {
                int row  = rowBase + wr + mt * 16 + g;
                int col  = colBase + wc + nt * 8 + 2 * tg;
                int colp = col >> 1;
                float2 bv = *(const float2*)&bias[col];
                C[(size_t)row * KP + colp] =
                    f2h2((acc[mt][nt][0] + bv.x) * oscale,
                         (acc[mt][nt][1] + bv.y) * oscale);
                C[(size_t)(row + 8) * KP + colp] =
                    f2h2((acc[mt][nt][2] + bv.x) * oscale,
                         (acc[mt][nt][3] + bv.y) * oscale);
            }
        }
    } else {
        float* C = (float*)Cout;
        #pragma unroll
        for (int mt = 0; mt < 4; mt++) {
            #pragma unroll
            for (int nt = 0; nt < 8; nt++) {
                int row = rowBase + wr + mt * 16 + g;
                int col = colBase + wc + nt * 8 + 2 * tg;
                float2 bv = *(const float2*)&bias[col];
                float2 r0 = make_float2(acc[mt][nt][0] + bv.x, acc[mt][nt][1] + bv.y);
                float2 r1 = make_float2(acc[mt][nt][2] + bv.x, acc[mt][nt][3] + bv.y);
                *(float2*)&C[(size_t)row * EMBED + col]       = r0;
                *(float2*)&C[(size_t)(row + 8) * EMBED + col] = r1;
            }
        }
    }
}

__global__ void __launch_bounds__(128) gemm_qkv_kernel(
    const float* __restrict__ bq, const float* __restrict__ bk,
    const float* __restrict__ bv)
{
    const int z = blockIdx.z;
    if (z == 0)      gemm_h_body(g_Xqh, g_Wh[0], bq, g_Qh, 1, 0.125f, blockIdx.x, blockIdx.y);
    else if (z == 1) gemm_h_body(g_Xch, g_Wh[1], bk, g_Kh, 1, 1.0f,   blockIdx.x, blockIdx.y);
    else             gemm_h_body(g_Xch, g_Wh[2], bv, g_Vf, 0, 1.0f,   blockIdx.x, blockIdx.y);
}

__global__ void __launch_bounds__(128) gemm_o_kernel(
    const float* __restrict__ bo, float* __restrict__ out)
{
    gemm_h_body(g_Ah, g_Wh[3], bo, out, 0, 1.0f, blockIdx.x, blockIdx.y);
}

// ---------------------------------------------------------------------------
// Flash attention fp16, P in registers. q-tile 128, 4 warps x 32 rows;
// kv tiles of 64; K/V double-buffered. (R7 version — near mma.sync ceiling.)
// ---------------------------------------------------------------------------
#define PKH 36
#define PVH 72
#define PPH 36
#define FSM_TOTAL ((2 * 64 * PKH + 2 * 32 * PVH + 128 * PPH) * 4)

__global__ void __launch_bounds__(128) flash_h_kernel()
{
    extern __shared__ uint32_t sm[];
    uint32_t* Ks = sm;
    uint32_t* Vs = sm + 2 * 64 * PKH;
    uint32_t* Qstage = sm + 2 * 64 * PKH + 2 * 32 * PVH;

    const int b  = blockIdx.z;
    const int h  = blockIdx.y;
    const int q0 = blockIdx.x * 128;
    const int tid  = threadIdx.x;
    const int lane = tid & 31;
    const int warp = tid >> 5;
    const int g    = lane >> 2;
    const int tg   = lane & 3;
    const int mrow = warp * 32;

    const uint32_t* Qb = g_Qh + (size_t)b * QLEN * KP + h * 32;
    const uint32_t* Kb = g_Kh + (size_t)b * CLEN * KP + h * 32;
    const float*    Vb = g_Vf + (size_t)b * CLEN * EMBED + h * HDIM;

    const int kvr = tid >> 3;
    const int dq  = (tid & 7) * 4;
    uint4 kpf[4];
    auto ldgK = [&](int kt) {
        #pragma unroll
        for (int i = 0; i < 4; i++)
            kpf[i] = *(const uint4*)&Kb[(size_t)(kt * 64 + kvr + 16 * i) * KP + dq];
    };
    auto stsK = [&](uint32_t* dst) {
        #pragma unroll
        for (int i = 0; i < 4; i++)
            *(uint4*)&dst[(kvr + 16 * i) * PKH + dq] = kpf[i];
    };

    const int va_ = tid >> 4;
    const int dcol = (tid & 15) * 4;
    float4 vpa[4], vpb[4];
    auto ldgV = [&](int kt) {
        #pragma unroll
        for (int i = 0; i < 4; i++) {
            int kv2 = kt * 64 + 2 * (va_ + 8 * i);
            vpa[i] = *(const float4*)&Vb[(size_t)kv2 * EMBED + dcol];
            vpb[i] = *(const float4*)&Vb[(size_t)(kv2 + 1) * EMBED + dcol];
        }
    };
    auto stsV = [&](uint32_t* dst) {
        #pragma unroll
        for (int i = 0; i < 4; i++) {
            uint4 u = make_uint4(f2h2(vpa[i].x, vpb[i].x), f2h2(vpa[i].y, vpb[i].y),
                                 f2h2(vpa[i].z, vpb[i].z), f2h2(vpa[i].w, vpb[i].w));
            *(uint4*)&dst[(va_ + 8 * i) * PVH + dcol] = u;
        }
    };

    #pragma unroll
    for (int i = 0; i < 8; i++) {
        int idx = tid + i * 128;
        int r = idx >> 3;
        int q4 = (idx & 7) * 4;
        uint4 v = *(const uint4*)&Qb[(size_t)(q0 + r) * KP + q4];
        *(uint4*)&Qstage[r * PPH + q4] = v;
    }
    ldgK(0);
    __syncthreads();

    uint32_t qf[2][4][4];
    #pragma unroll
    for (int mt = 0; mt < 2; mt++) {
        int m = mrow + mt * 16 + g;
        #pragma unroll
        for (int s = 0; s < 4; s++) {
            qf[mt][s][0] = Qstage[m * PPH + 8 * s + tg];
            qf[mt][s][1] = Qstage[(m + 8) * PPH + 8 * s + tg];
            qf[mt][s][2] = Qstage[m * PPH + 8 * s + tg + 4];
            qf[mt][s][3] = Qstage[(m + 8) * PPH + 8 * s + tg + 4];
        }
    }
    stsK(Ks);
    ldgV(0);
    stsV(Vs);
    __syncthreads();

    float m_[4], l_[4];
    #pragma unroll
    for (int i = 0; i < 4; i++) { m_[i] = -INFINITY; l_[i] = 0.f; }
    float o[2][8][4];
    #pragma unroll
    for (int mt = 0; mt < 2; mt++)
        #pragma unroll
        for (int nt = 0; nt < 8; nt++)
            #pragma unroll
            for (int e = 0; e < 4; e++) o[mt][nt][e] = 0.f;

    const int NT = CLEN / 64;
    for (int kt = 0; kt < NT; kt++) {
        const int buf = kt & 1;
        uint32_t* Kcur = Ks + buf * 64 * PKH;
        uint32_t* Vcur = Vs + buf * 32 * PVH;
        uint32_t* Knxt = Ks + (buf ^ 1) * 64 * PKH;
        uint32_t* Vnxt = Vs + (buf ^ 1) * 32 * PVH;

        if (kt + 1 < NT) ldgK(kt + 1);

        float sacc[2][8][4];
        #pragma unroll
        for (int mt = 0; mt < 2; mt++)
            #pragma unroll
            for (int nt = 0; nt < 8; nt++)
                #pragma unroll
                for (int e = 0; e < 4; e++) sacc[mt][nt][e] = 0.f;

        #pragma unroll
        for (int s = 0; s < 4; s++) {
            #pragma unroll
            for (int nt = 0; nt < 8; nt++) {
                uint32_t bf[2];
                bf[0] = Kcur[(nt * 8 + g) * PKH + 8 * s + tg];
                bf[1] = Kcur[(nt * 8 + g) * PKH + 8 * s + tg + 4];
                MMA_F16(sacc[0][nt], qf[0][s], bf);
                MMA_F16(sacc[1][nt], qf[1][s], bf);
            }
        }

        if (kt + 1 < NT) {
            stsK(Knxt);
            ldgV(kt + 1);
        }

        #pragma unroll
        for (int mt = 0; mt < 2; mt++) {
            float mx0 = -INFINITY, mx1 = -INFINITY;
            #pragma unroll
            for (int nt = 0; nt < 8; nt++) {
                mx0 = fmaxf(mx0, fmaxf(sacc[mt][nt][0], sacc[mt][nt][1]));
                mx1 = fmaxf(mx1, fmaxf(sacc[mt][nt][2], sacc[mt][nt][3]));
            }
            #pragma unroll
            for (int off = 1; off < 4; off <<= 1) {
                mx0 = fmaxf(mx0, __shfl_xor_sync(0xffffffffu, mx0, off));
                mx1 = fmaxf(mx1, __shfl_xor_sync(0xffffffffu, mx1, off));
            }
            float mn0 = fmaxf(m_[2 * mt],     mx0);
            float mn1 = fmaxf(m_[2 * mt + 1], mx1);
            float c0 = __expf(m_[2 * mt]     - mn0);
            float c1 = __expf(m_[2 * mt + 1] - mn1);

            float rs0 = 0.f, rs1 = 0.f;
            #pragma unroll
            for (int nt = 0; nt < 8; nt++) {
                sacc[mt][nt][0] = __expf(sacc[mt][nt][0] - mn0);
                sacc[mt][nt][1] = __expf(sacc[mt][nt][1] - mn0);
                sacc[mt][nt][2] = __expf(sacc[mt][nt][2] - mn1);
                sacc[mt][nt][3] = __expf(sacc[mt][nt][3] - mn1);
                rs0 += sacc[mt][nt][0] + sacc[mt][nt][1];
                rs1 += sacc[mt][nt][2] + sacc[mt][nt][3];
            }
            #pragma unroll
            for (int off = 1; off < 4; off <<= 1) {
                rs0 += __shfl_xor_sync(0xffffffffu, rs0, off);
                rs1 += __shfl_xor_sync(0xffffffffu, rs1, off);
            }
            l_[2 * mt]     = l_[2 * mt]     * c0 + rs0;
            l_[2 * mt + 1] = l_[2 * mt + 1] * c1 + rs1;
            m_[2 * mt]     = mn0;
            m_[2 * mt + 1] = mn1;
            #pragma unroll
            for (int nt = 0; nt < 8; nt++) {
                o[mt][nt][0] *= c0; o[mt][nt][1] *= c0;
                o[mt][nt][2] *= c1; o[mt][nt][3] *= c1;
            }
        }

        #pragma unroll
        for (int s = 0; s < 4; s++) {
            uint32_t af[2][4];
            #pragma unroll
            for (int mt = 0; mt < 2; mt++) {
                af[mt][0] = f2h2(sacc[mt][2 * s][0],     sacc[mt][2 * s][1]);
                af[mt][1] = f2h2(sacc[mt][2 * s][2],     sacc[mt][2 * s][3]);
                af[mt][2] = f2h2(sacc[mt][2 * s + 1][0], sacc[mt][2 * s + 1][1]);
                af[mt][3] = f2h2(sacc[mt][2 * s + 1][2], sacc[mt][2 * s + 1][3]);
            }
            #pragma unroll
            for (int nt = 0; nt < 8; nt++) {
                uint32_t bf[2];
                bf[0] = Vcur[(8 * s + tg) * PVH + nt * 8 + g];
                bf[1] = Vcur[(8 * s + tg + 4) * PVH + nt * 8 + g];
                MMA_F16(o[0][nt], af[0], bf);
                MMA_F16(o[1][nt], af[1], bf);
            }
        }

        if (kt + 1 < NT) stsV(Vnxt);
        __syncthreads();
    }

    uint32_t* Ab = g_Ah + (size_t)b * QLEN * KP + h * 32;
    #pragma unroll
    for (int mt = 0; mt < 2; mt++) {
        float i0 = 1.f / l_[2 * mt];
        float i1 = 1.f / l_[2 * mt + 1];
        int r0 = q0 + mrow + mt * 16 + g;
        #pragma unroll
        for (int nt = 0; nt < 8; nt++) {
            int colp = nt * 4 + tg;
            Ab[(size_t)r0 * KP + colp]       = f2h2(o[mt][nt][0] * i0, o[mt][nt][1] * i0);
            Ab[(size_t)(r0 + 8) * KP + colp] = f2h2(o[mt][nt][2] * i1, o[mt][nt][3] * i1);
        }
    }
}

// ---------------------------------------------------------------------------
extern "C" void kernel_launch(void* const* d_in, const int* in_sizes, int n_in,
                              void* d_out, int out_size)
{
    const float* query   = (const float*)d_in[0];
    const float* context = (const float*)d_in[1];
    const float* Wq = (const float*)d_in[2];
    const float* bq = (const float*)d_in[3];
    const float* Wk = (const float*)d_in[4];
    const float* bk = (const float*)d_in[5];
    const float* Wv = (const float*)d_in[6];
    const float* bv = (const float*)d_in[7];
    const float* Wo = (const float*)d_in[8];
    const float* bo = (const float*)d_in[9];
    float* out = (float*)d_out;

    prepack_kernel<<<dim3(256, 1, 6), 256>>>(query, context, Wq, Wk, Wv, Wo);

    dim3 gQKV(EMBED / 128, MROWS / 128, 3);   // (8, 32, 3) = 768 CTAs
    gemm_qkv_kernel<<<gQKV, 128>>>(bq, bk, bv);

    cudaFuncSetAttribute(flash_h_kernel,
                         cudaFuncAttributeMaxDynamicSharedMemorySize, FSM_TOTAL);
    flash_h_kernel<<<dim3(QLEN / 128, NHEADS, BATCH), 128, FSM_TOTAL>>>();

    dim3 gGemm(EMBED / 128, MROWS / 128);     // (8, 32) = 256 CTAs
    gemm_o_kernel<<<gGemm, 128>>>(bo, out);
}